// round 2
// baseline (speedup 1.0000x reference)
#include <cuda_runtime.h>
#include <cstdint>

// ---------------------------------------------------------------------------
// VNN_cell: 3-level hierarchical MLP with mish + training-mode BatchNorm.
//   L1: 200 groups, Linear(160->10)  -> mish -> BN   (input 1024x4000x8 fp32)
//   L2:  20 groups, Linear(100->10)  -> mish -> BN
//   L3:   1 group,  Linear(200->10)  -> mish -> BN   -> output [1024,10]
// Strategy: DRAM-bound L1 GEMM with f32x2 packed FMA; deterministic two-pass
// BN via per-column (scale,shift) folding; BN applied inline by the consumer.
// kernel_launch = 6 kernel launches, zero other runtime API calls.
// ---------------------------------------------------------------------------

#define B_  1024
#define GQ  4000
#define OQ  8
#define L1G 200
#define K1_ 160          // C1*O
#define L2G 20
#define K2_ 100          // C2*H
#define K3_ 200          // L2*H
#define H_  10
#define EPS 1e-5f

// Scratch (device globals; no allocation anywhere)
__device__ float d_a1[B_ * L1G * H_];   // post-mish level-1 activations [1024,2000]
__device__ float d_a2[B_ * L2G * H_];   // post-mish level-2 activations [1024,200]
__device__ float d_a3[B_ * H_];         // post-mish root activations    [1024,10]
__device__ float d_scale1[L1G * H_];
__device__ float d_shift1[L1G * H_];
__device__ float d_scale2[L2G * H_];
__device__ float d_shift2[L2G * H_];

// ---------------------------------------------------------------------------
// helpers
// ---------------------------------------------------------------------------
__device__ __forceinline__ float mishf(float x) {
    // mish(x) = x * tanh(softplus(x)); softplus stable for large |x|
    float sp = (x > 15.0f) ? x : log1pf(expf(x));
    return x * tanhf(sp);
}

__device__ __forceinline__ unsigned long long pack_dup(float x) {
    unsigned long long r;
    asm("mov.b64 %0, {%1, %1};" : "=l"(r) : "f"(x));
    return r;
}
__device__ __forceinline__ unsigned long long pack2(float a, float b) {
    unsigned long long r;
    asm("mov.b64 %0, {%1, %2};" : "=l"(r) : "f"(a), "f"(b));
    return r;
}
__device__ __forceinline__ void unpack2(unsigned long long v, float& a, float& b) {
    asm("mov.b64 {%0, %1}, %2;" : "=f"(a), "=f"(b) : "l"(v));
}

// acc[p] (+)= {x,x} * W[k][2p:2p+2]   -- 5 packed FMAs = 10 MACs per k-step
__device__ __forceinline__ void fma10(unsigned long long acc[5], float x,
                                      const float* __restrict__ Wrow) {
    unsigned long long x2 = pack_dup(x);
#pragma unroll
    for (int p = 0; p < 5; p++) {
        unsigned long long w2 =
            __double_as_longlong(*reinterpret_cast<const double*>(Wrow + 2 * p));
        asm("fma.rn.f32x2 %0, %1, %2, %0;" : "+l"(acc[p]) : "l"(x2), "l"(w2));
    }
}

// ---------------------------------------------------------------------------
// K1: level-1.  grid(200, 4), block 256.  thread = one batch row of one group.
// Reads 131 MB features (the DRAM floor), writes 8 MB d_a1.
// ---------------------------------------------------------------------------
__global__ void __launch_bounds__(256)
k_lvl1(const float* __restrict__ feat, const float* __restrict__ W1,
       const float* __restrict__ b1) {
    __shared__ alignas(16) float Wsh[K1_ * H_];   // 6.4 KB
    __shared__ float bsh[H_];
    const int g = blockIdx.x;
    const float* Wg = W1 + g * (K1_ * H_);
    for (int i = threadIdx.x; i < K1_ * H_; i += 256) Wsh[i] = Wg[i];
    if (threadIdx.x < H_) bsh[threadIdx.x] = b1[g * H_ + threadIdx.x];
    __syncthreads();

    const int b = blockIdx.y * 256 + threadIdx.x;
    const float4* xp = reinterpret_cast<const float4*>(
        feat + (size_t)b * (GQ * OQ) + (size_t)g * K1_);

    unsigned long long acc[5];
#pragma unroll
    for (int p = 0; p < 5; p++) acc[p] = pack2(bsh[2 * p], bsh[2 * p + 1]);

#pragma unroll 5
    for (int j = 0; j < K1_ / 4; j++) {
        float4 xv = xp[j];
        fma10(acc, xv.x, &Wsh[(4 * j + 0) * H_]);
        fma10(acc, xv.y, &Wsh[(4 * j + 1) * H_]);
        fma10(acc, xv.z, &Wsh[(4 * j + 2) * H_]);
        fma10(acc, xv.w, &Wsh[(4 * j + 3) * H_]);
    }

    float* dst = d_a1 + (size_t)b * (L1G * H_) + g * H_;
#pragma unroll
    for (int p = 0; p < 5; p++) {
        float lo, hi;
        unpack2(acc[p], lo, hi);
        float2 o;
        o.x = mishf(lo);
        o.y = mishf(hi);
        *reinterpret_cast<float2*>(dst + 2 * p) = o;
    }
}

// ---------------------------------------------------------------------------
// stats kernels: fold batch mean/var + affine into per-column (scale, shift).
// Deterministic fixed-order reduction (no atomics). block = 256, 64 cols/block.
// Two hardcoded instances (level 1 / level 2) so no pointers-to-globals are
// needed on the host side.
// ---------------------------------------------------------------------------
__device__ __forceinline__ void stats_body(const float* __restrict__ a,
                                           const float* __restrict__ gamma,
                                           const float* __restrict__ beta,
                                           float* __restrict__ scale,
                                           float* __restrict__ shift, int ncols) {
    const int c = threadIdx.x & 63;
    const int rq = threadIdx.x >> 6;          // 0..3
    const int col = blockIdx.x * 64 + c;
    float s = 0.f, s2 = 0.f;
    if (col < ncols) {
        for (int b = rq; b < B_; b += 4) {
            float v = a[(size_t)b * ncols + col];
            s += v;
            s2 += v * v;
        }
    }
    __shared__ float sh1[4][64], sh2[4][64];
    sh1[rq][c] = s;
    sh2[rq][c] = s2;
    __syncthreads();
    if (threadIdx.x < 64 && col < ncols) {
        float S = sh1[0][c] + sh1[1][c] + sh1[2][c] + sh1[3][c];
        float S2 = sh2[0][c] + sh2[1][c] + sh2[2][c] + sh2[3][c];
        float mean = S * (1.0f / B_);
        float var = S2 * (1.0f / B_) - mean * mean;
        float istd = rsqrtf(var + EPS);
        float sc = gamma[col] * istd;
        scale[col] = sc;
        shift[col] = beta[col] - mean * sc;
    }
}

__global__ void __launch_bounds__(256)
k_stats1(const float* __restrict__ gamma, const float* __restrict__ beta) {
    stats_body(d_a1, gamma, beta, d_scale1, d_shift1, L1G * H_);
}

__global__ void __launch_bounds__(256)
k_stats2(const float* __restrict__ gamma, const float* __restrict__ beta) {
    stats_body(d_a2, gamma, beta, d_scale2, d_shift2, L2G * H_);
}

// ---------------------------------------------------------------------------
// K3: level-2.  grid(20, 8), block 128. BN of level-1 applied inline on read.
// ---------------------------------------------------------------------------
__global__ void __launch_bounds__(128)
k_lvl2(const float* __restrict__ W2, const float* __restrict__ b2) {
    __shared__ alignas(16) float Wsh[K2_ * H_];   // 4 KB
    __shared__ float bsh[H_];
    __shared__ alignas(16) float sc[K2_], sf[K2_];
    const int g = blockIdx.x;
    for (int i = threadIdx.x; i < K2_ * H_; i += 128) Wsh[i] = W2[g * (K2_ * H_) + i];
    if (threadIdx.x < K2_) {
        sc[threadIdx.x] = d_scale1[g * K2_ + threadIdx.x];
        sf[threadIdx.x] = d_shift1[g * K2_ + threadIdx.x];
    }
    if (threadIdx.x < H_) bsh[threadIdx.x] = b2[g * H_ + threadIdx.x];
    __syncthreads();

    const int b = blockIdx.y * 128 + threadIdx.x;
    const float4* xp = reinterpret_cast<const float4*>(
        d_a1 + (size_t)b * (L1G * H_) + g * K2_);

    unsigned long long acc[5];
#pragma unroll
    for (int p = 0; p < 5; p++) acc[p] = pack2(bsh[2 * p], bsh[2 * p + 1]);

#pragma unroll 5
    for (int j = 0; j < K2_ / 4; j++) {
        float4 xv = xp[j];
        const int k = 4 * j;
        fma10(acc, fmaf(xv.x, sc[k + 0], sf[k + 0]), &Wsh[(k + 0) * H_]);
        fma10(acc, fmaf(xv.y, sc[k + 1], sf[k + 1]), &Wsh[(k + 1) * H_]);
        fma10(acc, fmaf(xv.z, sc[k + 2], sf[k + 2]), &Wsh[(k + 2) * H_]);
        fma10(acc, fmaf(xv.w, sc[k + 3], sf[k + 3]), &Wsh[(k + 3) * H_]);
    }

    float* dst = d_a2 + (size_t)b * (L2G * H_) + g * H_;
#pragma unroll
    for (int p = 0; p < 5; p++) {
        float lo, hi;
        unpack2(acc[p], lo, hi);
        float2 o;
        o.x = mishf(lo);
        o.y = mishf(hi);
        *reinterpret_cast<float2*>(dst + 2 * p) = o;
    }
}

// ---------------------------------------------------------------------------
// K5: root linear.  grid(8), block 128. BN of level-2 applied inline.
// ---------------------------------------------------------------------------
__global__ void __launch_bounds__(128)
k_lvl3(const float* __restrict__ W3, const float* __restrict__ b3) {
    __shared__ alignas(16) float Wsh[K3_ * H_];   // 8 KB
    __shared__ float bsh[H_];
    __shared__ alignas(16) float sc[K3_], sf[K3_];
    for (int i = threadIdx.x; i < K3_ * H_; i += 128) Wsh[i] = W3[i];
    for (int i = threadIdx.x; i < K3_; i += 128) {
        sc[i] = d_scale2[i];
        sf[i] = d_shift2[i];
    }
    if (threadIdx.x < H_) bsh[threadIdx.x] = b3[threadIdx.x];
    __syncthreads();

    const int b = blockIdx.x * 128 + threadIdx.x;
    const float4* xp = reinterpret_cast<const float4*>(d_a2 + (size_t)b * K3_);

    unsigned long long acc[5];
#pragma unroll
    for (int p = 0; p < 5; p++) acc[p] = pack2(bsh[2 * p], bsh[2 * p + 1]);

#pragma unroll 5
    for (int j = 0; j < K3_ / 4; j++) {
        float4 xv = xp[j];
        const int k = 4 * j;
        fma10(acc, fmaf(xv.x, sc[k + 0], sf[k + 0]), &Wsh[(k + 0) * H_]);
        fma10(acc, fmaf(xv.y, sc[k + 1], sf[k + 1]), &Wsh[(k + 1) * H_]);
        fma10(acc, fmaf(xv.z, sc[k + 2], sf[k + 2]), &Wsh[(k + 2) * H_]);
        fma10(acc, fmaf(xv.w, sc[k + 3], sf[k + 3]), &Wsh[(k + 3) * H_]);
    }

    float* dst = d_a3 + (size_t)b * H_;
#pragma unroll
    for (int p = 0; p < 5; p++) {
        float lo, hi;
        unpack2(acc[p], lo, hi);
        float2 o;
        o.x = mishf(lo);
        o.y = mishf(hi);
        *reinterpret_cast<float2*>(dst + 2 * p) = o;
    }
}

// ---------------------------------------------------------------------------
// K6: root BN stats + normalize + write output. 1 block, 1024 threads.
// ---------------------------------------------------------------------------
__global__ void __launch_bounds__(1024)
k_final(const float* __restrict__ g3, const float* __restrict__ bt3,
        float* __restrict__ out) {
    const int b = threadIdx.x;
    float v[H_];
    const float2* row = reinterpret_cast<const float2*>(d_a3 + (size_t)b * H_);
#pragma unroll
    for (int p = 0; p < 5; p++) {
        float2 t = row[p];
        v[2 * p] = t.x;
        v[2 * p + 1] = t.y;
    }
    float s[H_], s2[H_];
#pragma unroll
    for (int i = 0; i < H_; i++) {
        s[i] = v[i];
        s2[i] = v[i] * v[i];
    }
#pragma unroll
    for (int off = 16; off; off >>= 1) {
#pragma unroll
        for (int i = 0; i < H_; i++) {
            s[i] += __shfl_down_sync(0xffffffffu, s[i], off);
            s2[i] += __shfl_down_sync(0xffffffffu, s2[i], off);
        }
    }
    __shared__ float ws[32][H_], ws2[32][H_];
    const int lane = b & 31, wrp = b >> 5;
    if (lane == 0) {
#pragma unroll
        for (int i = 0; i < H_; i++) {
            ws[wrp][i] = s[i];
            ws2[wrp][i] = s2[i];
        }
    }
    __syncthreads();
    __shared__ float fsc[H_], fsf[H_];
    if (threadIdx.x < H_) {
        float S = 0.f, S2 = 0.f;
        for (int w = 0; w < 32; w++) {
            S += ws[w][threadIdx.x];
            S2 += ws2[w][threadIdx.x];
        }
        float mean = S * (1.0f / B_);
        float var = S2 * (1.0f / B_) - mean * mean;
        float istd = rsqrtf(var + EPS);
        float scv = g3[threadIdx.x] * istd;
        fsc[threadIdx.x] = scv;
        fsf[threadIdx.x] = bt3[threadIdx.x] - mean * scv;
    }
    __syncthreads();
#pragma unroll
    for (int i = 0; i < H_; i++)
        out[(size_t)b * H_ + i] = fmaf(v[i], fsc[i], fsf[i]);
}

// ---------------------------------------------------------------------------
// launch: exactly 6 kernel launches, no other runtime API calls.
// Inputs (metadata order): features, W1, b1, g1, bt1, W2, b2, g2, bt2,
//                          W3, b3, g3, bt3
// ---------------------------------------------------------------------------
extern "C" void kernel_launch(void* const* d_in, const int* in_sizes, int n_in,
                              void* d_out, int out_size) {
    const float* feat = (const float*)d_in[0];
    const float* W1  = (const float*)d_in[1];
    const float* b1  = (const float*)d_in[2];
    const float* g1  = (const float*)d_in[3];
    const float* bt1 = (const float*)d_in[4];
    const float* W2  = (const float*)d_in[5];
    const float* b2  = (const float*)d_in[6];
    const float* g2  = (const float*)d_in[7];
    const float* bt2 = (const float*)d_in[8];
    const float* W3  = (const float*)d_in[9];
    const float* b3  = (const float*)d_in[10];
    const float* g3  = (const float*)d_in[11];
    const float* bt3 = (const float*)d_in[12];
    float* out = (float*)d_out;

    k_lvl1<<<dim3(L1G, B_ / 256), 256>>>(feat, W1, b1);
    k_stats1<<<(L1G * H_ + 63) / 64, 256>>>(g1, bt1);
    k_lvl2<<<dim3(L2G, B_ / 128), 128>>>(W2, b2);
    k_stats2<<<(L2G * H_ + 63) / 64, 256>>>(g2, bt2);
    k_lvl3<<<B_ / 128, 128>>>(W3, b3);
    k_final<<<1, B_>>>(g3, bt3, out);
}

// round 3
// speedup vs baseline: 1.2158x; 1.2158x over previous
#include <cuda_runtime.h>
#include <cstdint>

// ---------------------------------------------------------------------------
// VNN_cell: 3-level hierarchical MLP with mish + training-mode BatchNorm.
// R2: fused BN statistics. Producer kernels reduce their own output tile to
// per-block partial (sum, sumsq); consumer kernels finalize mean/var into
// (scale, shift) inline. 4 kernels total, no stats re-read of activations.
// ---------------------------------------------------------------------------

#define B_  1024
#define GQ  4000
#define OQ  8
#define L1G 200
#define K1_ 160          // C1*O
#define L2G 20
#define K2_ 100          // C2*H
#define K3_ 200          // L2*H
#define H_  10
#define EPS 1e-5f
#define INV_B (1.0f / 1024.0f)

// Scratch (device globals; no allocation anywhere)
__device__ float d_a1[B_ * L1G * H_];    // post-mish level-1 activations [1024,2000]
__device__ float d_a2[B_ * L2G * H_];    // post-mish level-2 activations [1024,200]
__device__ float d_a3[B_ * H_];          // post-mish root activations    [1024,10]
__device__ float d_p1s[4][L1G * H_];     // k_lvl1 partial sums   (4 row-blocks of 256)
__device__ float d_p1q[4][L1G * H_];     // k_lvl1 partial sumsq
__device__ float d_p2s[8][L2G * H_];     // k_lvl2 partials (8 row-blocks of 128)
__device__ float d_p2q[8][L2G * H_];
__device__ float d_p3s[8][H_];           // k_lvl3 partials (8 row-blocks of 128)
__device__ float d_p3q[8][H_];

// ---------------------------------------------------------------------------
// helpers
// ---------------------------------------------------------------------------
__device__ __forceinline__ float mishf(float x) {
    float sp = (x > 15.0f) ? x : log1pf(expf(x));
    return x * tanhf(sp);
}

__device__ __forceinline__ unsigned long long pack_dup(float x) {
    unsigned long long r;
    asm("mov.b64 %0, {%1, %1};" : "=l"(r) : "f"(x));
    return r;
}
__device__ __forceinline__ unsigned long long pack2(float a, float b) {
    unsigned long long r;
    asm("mov.b64 %0, {%1, %2};" : "=l"(r) : "f"(a), "f"(b));
    return r;
}
__device__ __forceinline__ void unpack2(unsigned long long v, float& a, float& b) {
    asm("mov.b64 {%0, %1}, %2;" : "=f"(a), "=f"(b) : "l"(v));
}

// acc[p] (+)= {x,x} * W[k][2p:2p+2]   -- 5 packed FMAs = 10 MACs per k-step
__device__ __forceinline__ void fma10(unsigned long long acc[5], float x,
                                      const float* __restrict__ Wrow) {
    unsigned long long x2 = pack_dup(x);
#pragma unroll
    for (int p = 0; p < 5; p++) {
        unsigned long long w2 =
            __double_as_longlong(*reinterpret_cast<const double*>(Wrow + 2 * p));
        asm("fma.rn.f32x2 %0, %1, %2, %0;" : "+l"(acc[p]) : "l"(x2), "l"(w2));
    }
}

// Block-level partial-stat reduction for 10 columns.
// Each thread holds v[10]; result: threads 0..9 get column sums, 10..19 sumsq.
// NWARP = blockDim.x/32. Deterministic fixed-order adds.
template <int NWARP>
__device__ __forceinline__ void block_stats10(const float v[H_], float* outS,
                                              float* outQ, int tid) {
    float s[H_], q[H_];
#pragma unroll
    for (int i = 0; i < H_; i++) {
        s[i] = v[i];
        q[i] = v[i] * v[i];
    }
#pragma unroll
    for (int off = 16; off; off >>= 1) {
#pragma unroll
        for (int i = 0; i < H_; i++) {
            s[i] += __shfl_down_sync(0xffffffffu, s[i], off);
            q[i] += __shfl_down_sync(0xffffffffu, q[i], off);
        }
    }
    __shared__ float red[NWARP][2 * H_];
    const int lane = tid & 31, wrp = tid >> 5;
    if (lane == 0) {
#pragma unroll
        for (int i = 0; i < H_; i++) {
            red[wrp][i] = s[i];
            red[wrp][H_ + i] = q[i];
        }
    }
    __syncthreads();
    if (tid < 2 * H_) {
        float t = 0.f;
#pragma unroll
        for (int w = 0; w < NWARP; w++) t += red[w][tid];
        if (tid < H_) outS[tid] = t;
        else outQ[tid - H_] = t;
    }
}

// ---------------------------------------------------------------------------
// K1: level-1.  grid(200, 4), block 256.  thread = one batch row of one group.
// Reads 131 MB features (the DRAM floor), writes d_a1 + per-block partials.
// ---------------------------------------------------------------------------
__global__ void __launch_bounds__(256)
k_lvl1(const float* __restrict__ feat, const float* __restrict__ W1,
       const float* __restrict__ b1) {
    __shared__ alignas(16) float Wsh[K1_ * H_];   // 6.4 KB
    __shared__ float bsh[H_];
    const int g = blockIdx.x;
    const float* Wg = W1 + g * (K1_ * H_);
    for (int i = threadIdx.x; i < K1_ * H_; i += 256) Wsh[i] = Wg[i];
    if (threadIdx.x < H_) bsh[threadIdx.x] = b1[g * H_ + threadIdx.x];
    __syncthreads();

    const int b = blockIdx.y * 256 + threadIdx.x;
    const float4* xp = reinterpret_cast<const float4*>(
        feat + (size_t)b * (GQ * OQ) + (size_t)g * K1_);

    unsigned long long acc[5];
#pragma unroll
    for (int p = 0; p < 5; p++) acc[p] = pack2(bsh[2 * p], bsh[2 * p + 1]);

#pragma unroll 5
    for (int j = 0; j < K1_ / 4; j++) {
        float4 xv = xp[j];
        fma10(acc, xv.x, &Wsh[(4 * j + 0) * H_]);
        fma10(acc, xv.y, &Wsh[(4 * j + 1) * H_]);
        fma10(acc, xv.z, &Wsh[(4 * j + 2) * H_]);
        fma10(acc, xv.w, &Wsh[(4 * j + 3) * H_]);
    }

    float v[H_];
#pragma unroll
    for (int p = 0; p < 5; p++) {
        float lo, hi;
        unpack2(acc[p], lo, hi);
        v[2 * p] = mishf(lo);
        v[2 * p + 1] = mishf(hi);
    }
    float* dst = d_a1 + (size_t)b * (L1G * H_) + g * H_;
#pragma unroll
    for (int p = 0; p < 5; p++)
        *reinterpret_cast<float2*>(dst + 2 * p) = make_float2(v[2 * p], v[2 * p + 1]);

    __syncthreads();   // Wsh reuse barrier for red[] (distinct arrays, but order writes)
    block_stats10<8>(v, &d_p1s[blockIdx.y][g * H_], &d_p1q[blockIdx.y][g * H_],
                     threadIdx.x);
}

// ---------------------------------------------------------------------------
// K2: level-2.  grid(20, 8), block 128.
// Finalizes level-1 BN (from partials) inline, applies on read.
// ---------------------------------------------------------------------------
__global__ void __launch_bounds__(128)
k_lvl2(const float* __restrict__ W2, const float* __restrict__ b2,
       const float* __restrict__ g1, const float* __restrict__ bt1) {
    __shared__ alignas(16) float Wsh[K2_ * H_];   // 4 KB
    __shared__ float bsh[H_];
    __shared__ float sc[K2_], sf[K2_];
    const int g = blockIdx.x;
    for (int i = threadIdx.x; i < K2_ * H_; i += 128) Wsh[i] = W2[g * (K2_ * H_) + i];
    if (threadIdx.x < H_) bsh[threadIdx.x] = b2[g * H_ + threadIdx.x];
    if (threadIdx.x < K2_) {
        const int col = g * K2_ + threadIdx.x;
        float S = d_p1s[0][col] + d_p1s[1][col] + d_p1s[2][col] + d_p1s[3][col];
        float Q = d_p1q[0][col] + d_p1q[1][col] + d_p1q[2][col] + d_p1q[3][col];
        float mean = S * INV_B;
        float var = Q * INV_B - mean * mean;
        float istd = rsqrtf(var + EPS);
        float scv = g1[col] * istd;
        sc[threadIdx.x] = scv;
        sf[threadIdx.x] = bt1[col] - mean * scv;
    }
    __syncthreads();

    const int b = blockIdx.y * 128 + threadIdx.x;
    const float4* xp = reinterpret_cast<const float4*>(
        d_a1 + (size_t)b * (L1G * H_) + g * K2_);

    unsigned long long acc[5];
#pragma unroll
    for (int p = 0; p < 5; p++) acc[p] = pack2(bsh[2 * p], bsh[2 * p + 1]);

#pragma unroll 5
    for (int j = 0; j < K2_ / 4; j++) {
        float4 xv = xp[j];
        const int k = 4 * j;
        fma10(acc, fmaf(xv.x, sc[k + 0], sf[k + 0]), &Wsh[(k + 0) * H_]);
        fma10(acc, fmaf(xv.y, sc[k + 1], sf[k + 1]), &Wsh[(k + 1) * H_]);
        fma10(acc, fmaf(xv.z, sc[k + 2], sf[k + 2]), &Wsh[(k + 2) * H_]);
        fma10(acc, fmaf(xv.w, sc[k + 3], sf[k + 3]), &Wsh[(k + 3) * H_]);
    }

    float v[H_];
#pragma unroll
    for (int p = 0; p < 5; p++) {
        float lo, hi;
        unpack2(acc[p], lo, hi);
        v[2 * p] = mishf(lo);
        v[2 * p + 1] = mishf(hi);
    }
    float* dst = d_a2 + (size_t)b * (L2G * H_) + g * H_;
#pragma unroll
    for (int p = 0; p < 5; p++)
        *reinterpret_cast<float2*>(dst + 2 * p) = make_float2(v[2 * p], v[2 * p + 1]);

    __syncthreads();
    block_stats10<4>(v, &d_p2s[blockIdx.y][g * H_], &d_p2q[blockIdx.y][g * H_],
                     threadIdx.x);
}

// ---------------------------------------------------------------------------
// K3: root linear.  grid(8), block 128. Finalizes level-2 BN inline.
// ---------------------------------------------------------------------------
__global__ void __launch_bounds__(128)
k_lvl3(const float* __restrict__ W3, const float* __restrict__ b3,
       const float* __restrict__ g2, const float* __restrict__ bt2) {
    __shared__ alignas(16) float Wsh[K3_ * H_];   // 8 KB
    __shared__ float bsh[H_];
    __shared__ float sc[K3_], sf[K3_];
    for (int i = threadIdx.x; i < K3_ * H_; i += 128) Wsh[i] = W3[i];
    if (threadIdx.x < H_) bsh[threadIdx.x] = b3[threadIdx.x];
    for (int col = threadIdx.x; col < K3_; col += 128) {
        float S = 0.f, Q = 0.f;
#pragma unroll
        for (int w = 0; w < 8; w++) {
            S += d_p2s[w][col];
            Q += d_p2q[w][col];
        }
        float mean = S * INV_B;
        float var = Q * INV_B - mean * mean;
        float istd = rsqrtf(var + EPS);
        float scv = g2[col] * istd;
        sc[col] = scv;
        sf[col] = bt2[col] - mean * scv;
    }
    __syncthreads();

    const int b = blockIdx.x * 128 + threadIdx.x;
    const float4* xp = reinterpret_cast<const float4*>(d_a2 + (size_t)b * K3_);

    unsigned long long acc[5];
#pragma unroll
    for (int p = 0; p < 5; p++) acc[p] = pack2(bsh[2 * p], bsh[2 * p + 1]);

#pragma unroll 5
    for (int j = 0; j < K3_ / 4; j++) {
        float4 xv = xp[j];
        const int k = 4 * j;
        fma10(acc, fmaf(xv.x, sc[k + 0], sf[k + 0]), &Wsh[(k + 0) * H_]);
        fma10(acc, fmaf(xv.y, sc[k + 1], sf[k + 1]), &Wsh[(k + 1) * H_]);
        fma10(acc, fmaf(xv.z, sc[k + 2], sf[k + 2]), &Wsh[(k + 2) * H_]);
        fma10(acc, fmaf(xv.w, sc[k + 3], sf[k + 3]), &Wsh[(k + 3) * H_]);
    }

    float v[H_];
#pragma unroll
    for (int p = 0; p < 5; p++) {
        float lo, hi;
        unpack2(acc[p], lo, hi);
        v[2 * p] = mishf(lo);
        v[2 * p + 1] = mishf(hi);
    }
    float* dst = d_a3 + (size_t)b * H_;
#pragma unroll
    for (int p = 0; p < 5; p++)
        *reinterpret_cast<float2*>(dst + 2 * p) = make_float2(v[2 * p], v[2 * p + 1]);

    __syncthreads();
    block_stats10<4>(v, &d_p3s[blockIdx.x][0], &d_p3q[blockIdx.x][0], threadIdx.x);
}

// ---------------------------------------------------------------------------
// K4: finalize root BN + write output. 1 block, 1024 threads.
// ---------------------------------------------------------------------------
__global__ void __launch_bounds__(1024)
k_final(const float* __restrict__ g3, const float* __restrict__ bt3,
        float* __restrict__ out) {
    __shared__ float fsc[H_], fsf[H_];
    if (threadIdx.x < H_) {
        float S = 0.f, Q = 0.f;
#pragma unroll
        for (int w = 0; w < 8; w++) {
            S += d_p3s[w][threadIdx.x];
            Q += d_p3q[w][threadIdx.x];
        }
        float mean = S * INV_B;
        float var = Q * INV_B - mean * mean;
        float istd = rsqrtf(var + EPS);
        float scv = g3[threadIdx.x] * istd;
        fsc[threadIdx.x] = scv;
        fsf[threadIdx.x] = bt3[threadIdx.x] - mean * scv;
    }
    __syncthreads();
    const int b = threadIdx.x;
    const float2* row = reinterpret_cast<const float2*>(d_a3 + (size_t)b * H_);
    float2* orow = reinterpret_cast<float2*>(out + (size_t)b * H_);
#pragma unroll
    for (int p = 0; p < 5; p++) {
        float2 t = row[p];
        float2 o;
        o.x = fmaf(t.x, fsc[2 * p], fsf[2 * p]);
        o.y = fmaf(t.y, fsc[2 * p + 1], fsf[2 * p + 1]);
        orow[p] = o;
    }
}

// ---------------------------------------------------------------------------
// launch: exactly 4 kernel launches, no other runtime API calls.
// Inputs (metadata order): features, W1, b1, g1, bt1, W2, b2, g2, bt2,
//                          W3, b3, g3, bt3
// ---------------------------------------------------------------------------
extern "C" void kernel_launch(void* const* d_in, const int* in_sizes, int n_in,
                              void* d_out, int out_size) {
    const float* feat = (const float*)d_in[0];
    const float* W1  = (const float*)d_in[1];
    const float* b1  = (const float*)d_in[2];
    const float* g1  = (const float*)d_in[3];
    const float* bt1 = (const float*)d_in[4];
    const float* W2  = (const float*)d_in[5];
    const float* b2  = (const float*)d_in[6];
    const float* g2  = (const float*)d_in[7];
    const float* bt2 = (const float*)d_in[8];
    const float* W3  = (const float*)d_in[9];
    const float* b3  = (const float*)d_in[10];
    const float* g3  = (const float*)d_in[11];
    const float* bt3 = (const float*)d_in[12];
    float* out = (float*)d_out;

    k_lvl1<<<dim3(L1G, B_ / 256), 256>>>(feat, W1, b1);
    k_lvl2<<<dim3(L2G, B_ / 128), 128>>>(W2, b2, g1, bt1);
    k_lvl3<<<B_ / 128, 128>>>(W3, b3, g2, bt2);
    k_final<<<1, B_>>>(g3, bt3, out);
}

// round 5
// speedup vs baseline: 1.4252x; 1.1722x over previous
#include <cuda_runtime.h>
#include <cstdint>

// ---------------------------------------------------------------------------
// VNN_cell: 3-level hierarchical MLP with mish + training-mode BatchNorm.
// R4: fixes R3's bsh init race (acc starts at zero, bias added post-barrier)
// and replaces tanh.approx mish with exact rational form via ex2+rcp.
// ---------------------------------------------------------------------------

#define B_  1024
#define GQ  4000
#define OQ  8
#define L1G 200
#define K1_ 160          // C1*O
#define L2G 20
#define K2_ 100          // C2*H
#define K3_ 200          // L2*H
#define H_  10
#define EPS 1e-5f
#define INV_B (1.0f / 1024.0f)

#define RPB1 128         // rows per k_lvl1 block
#define NB1  (B_ / RPB1) // 8 row-blocks
#define XSTR 44          // smem row stride (floats): 16B-aligned, low conflicts

// Scratch (device globals; no allocation anywhere)
__device__ float d_a1[B_ * L1G * H_];    // post-mish level-1 activations
__device__ float d_a2[B_ * L2G * H_];    // post-mish level-2 activations
__device__ float d_a3[B_ * H_];          // post-mish root activations
__device__ float d_p1s[NB1][L1G * H_];   // k_lvl1 partial sums
__device__ float d_p1q[NB1][L1G * H_];   // k_lvl1 partial sumsq
__device__ float d_p2s[8][L2G * H_];
__device__ float d_p2q[8][L2G * H_];
__device__ float d_p3s[8][H_];
__device__ float d_p3q[8][H_];

// ---------------------------------------------------------------------------
// helpers
// ---------------------------------------------------------------------------
__device__ __forceinline__ float mishf(float x) {
    // mish(x) = x * tanh(ln(1+e^x)) = x * (w^2-1)/(w^2+1), w = 1+e^x.
    // ex2/rcp approx are ~1-2 ulp; clamp ex2 arg so w2 never overflows
    // (for x>30 the ratio is 1 to fp32 precision anyway).
    float e;
    asm("ex2.approx.f32 %0, %1;" : "=f"(e)
        : "f"(fminf(x, 30.0f) * 1.4426950408889634f));
    float w = 1.0f + e;
    float w2 = w * w;
    float r;
    asm("rcp.approx.f32 %0, %1;" : "=f"(r) : "f"(w2 + 1.0f));
    return x * (w2 - 1.0f) * r;
}

__device__ __forceinline__ unsigned long long pack_dup(float x) {
    unsigned long long r;
    asm("mov.b64 %0, {%1, %1};" : "=l"(r) : "f"(x));
    return r;
}
__device__ __forceinline__ unsigned long long pack2(float a, float b) {
    unsigned long long r;
    asm("mov.b64 %0, {%1, %2};" : "=l"(r) : "f"(a), "f"(b));
    return r;
}
__device__ __forceinline__ void unpack2(unsigned long long v, float& a, float& b) {
    asm("mov.b64 {%0, %1}, %2;" : "=f"(a), "=f"(b) : "l"(v));
}

// acc[p] (+)= {x,x} * W[k][2p:2p+2]   -- 5 packed FMAs = 10 MACs per k-step
__device__ __forceinline__ void fma10(unsigned long long acc[5], float x,
                                      const float* __restrict__ Wrow) {
    unsigned long long x2 = pack_dup(x);
#pragma unroll
    for (int p = 0; p < 5; p++) {
        unsigned long long w2 =
            __double_as_longlong(*reinterpret_cast<const double*>(Wrow + 2 * p));
        asm("fma.rn.f32x2 %0, %1, %2, %0;" : "+l"(acc[p]) : "l"(x2), "l"(w2));
    }
}

// Block-level partial-stat reduction for 10 columns. Deterministic order.
template <int NWARP>
__device__ __forceinline__ void block_stats10(const float v[H_], float* outS,
                                              float* outQ, int tid) {
    float s[H_], q[H_];
#pragma unroll
    for (int i = 0; i < H_; i++) {
        s[i] = v[i];
        q[i] = v[i] * v[i];
    }
#pragma unroll
    for (int off = 16; off; off >>= 1) {
#pragma unroll
        for (int i = 0; i < H_; i++) {
            s[i] += __shfl_down_sync(0xffffffffu, s[i], off);
            q[i] += __shfl_down_sync(0xffffffffu, q[i], off);
        }
    }
    __shared__ float red[NWARP][2 * H_];
    const int lane = tid & 31, wrp = tid >> 5;
    if (lane == 0) {
#pragma unroll
        for (int i = 0; i < H_; i++) {
            red[wrp][i] = s[i];
            red[wrp][H_ + i] = q[i];
        }
    }
    __syncthreads();
    if (tid < 2 * H_) {
        float t = 0.f;
#pragma unroll
        for (int w = 0; w < NWARP; w++) t += red[w][tid];
        if (tid < H_) outS[tid] = t;
        else outQ[tid - H_] = t;
    }
}

// ---------------------------------------------------------------------------
// K1: level-1.  grid(200, 8), block 256 = 2 K-halves x 128 rows.
// Coalesced staged loads of 4 K-chunks (40 floats each) with reg prefetch.
// acc starts at ZERO; bias added in epilogue (post-barrier) -- no bsh race.
// ---------------------------------------------------------------------------
__global__ void __launch_bounds__(256)
k_lvl1(const float* __restrict__ feat, const float* __restrict__ W1,
       const float* __restrict__ b1) {
    __shared__ alignas(16) float Wsh[K1_ * H_];        // 6.4 KB
    __shared__ float bsh[H_];
    __shared__ alignas(16) float Xsh[RPB1 * XSTR];     // 22.5 KB staging
    __shared__ float Ex[RPB1 * H_];                    // 5 KB K-half exchange

    const int g = blockIdx.x;
    const int tid = threadIdx.x;
    const int h = tid >> 7;          // K-half 0/1
    const int r = tid & 127;         // row within block

    const float* Wg = W1 + g * (K1_ * H_);
    for (int i = tid; i < K1_ * H_; i += 256) Wsh[i] = Wg[i];
    if (tid < H_) bsh[tid] = b1[g * H_ + tid];

    const size_t rowbase = (size_t)(blockIdx.y * RPB1);
    const float* gsrc = feat + rowbase * (GQ * OQ) + (size_t)g * K1_;

    // prefetch chunk 0: 1280 float4 per chunk; thread does 5, row-major order
    float4 pf[5];
#pragma unroll
    for (int i = 0; i < 5; i++) {
        int idx = tid + i * 256;
        int rl = idx / 10, c4 = idx % 10;
        pf[i] = *reinterpret_cast<const float4*>(gsrc + (size_t)rl * (GQ * OQ) +
                                                 c4 * 4);
    }

    unsigned long long acc[5];
#pragma unroll
    for (int p = 0; p < 5; p++) acc[p] = pack2(0.f, 0.f);

#pragma unroll
    for (int kc = 0; kc < 4; kc++) {
        __syncthreads();   // chunk kc-1 consumed; also guards Wsh at kc==0
#pragma unroll
        for (int i = 0; i < 5; i++) {
            int idx = tid + i * 256;
            int rl = idx / 10, c4 = idx % 10;
            *reinterpret_cast<float4*>(&Xsh[rl * XSTR + c4 * 4]) = pf[i];
        }
        if (kc < 3) {
#pragma unroll
            for (int i = 0; i < 5; i++) {
                int idx = tid + i * 256;
                int rl = idx / 10, c4 = idx % 10;
                pf[i] = *reinterpret_cast<const float4*>(
                    gsrc + (size_t)rl * (GQ * OQ) + (kc + 1) * 40 + c4 * 4);
            }
        }
        __syncthreads();   // chunk kc staged
#pragma unroll
        for (int j = 0; j < 5; j++) {
            const int c4 = h * 5 + j;
            float4 xv = *reinterpret_cast<const float4*>(&Xsh[r * XSTR + c4 * 4]);
            const int kk = kc * 40 + c4 * 4;
            fma10(acc, xv.x, &Wsh[(kk + 0) * H_]);
            fma10(acc, xv.y, &Wsh[(kk + 1) * H_]);
            fma10(acc, xv.z, &Wsh[(kk + 2) * H_]);
            fma10(acc, xv.w, &Wsh[(kk + 3) * H_]);
        }
    }

    float a[H_];
#pragma unroll
    for (int p = 0; p < 5; p++) unpack2(acc[p], a[2 * p], a[2 * p + 1]);

    if (h) {
#pragma unroll
        for (int p = 0; p < 5; p++)
            *reinterpret_cast<float2*>(&Ex[r * H_ + 2 * p]) =
                make_float2(a[2 * p], a[2 * p + 1]);
    }
    __syncthreads();

    float v[H_];
    if (!h) {
#pragma unroll
        for (int i = 0; i < H_; i++)
            v[i] = mishf(a[i] + Ex[r * H_ + i] + bsh[i]);
        float* dst = d_a1 + (rowbase + r) * (L1G * H_) + g * H_;
#pragma unroll
        for (int p = 0; p < 5; p++)
            *reinterpret_cast<float2*>(dst + 2 * p) =
                make_float2(v[2 * p], v[2 * p + 1]);
    } else {
#pragma unroll
        for (int i = 0; i < H_; i++) v[i] = 0.f;
    }
    __syncthreads();
    block_stats10<8>(v, &d_p1s[blockIdx.y][g * H_], &d_p1q[blockIdx.y][g * H_],
                     tid);
}

// ---------------------------------------------------------------------------
// K2: level-2.  grid(20, 8), block 128. Finalizes level-1 BN inline.
// ---------------------------------------------------------------------------
__global__ void __launch_bounds__(128)
k_lvl2(const float* __restrict__ W2, const float* __restrict__ b2,
       const float* __restrict__ g1, const float* __restrict__ bt1) {
    __shared__ alignas(16) float Wsh[K2_ * H_];
    __shared__ float bsh[H_];
    __shared__ float sc[K2_], sf[K2_];
    const int g = blockIdx.x;
    for (int i = threadIdx.x; i < K2_ * H_; i += 128) Wsh[i] = W2[g * (K2_ * H_) + i];
    if (threadIdx.x < H_) bsh[threadIdx.x] = b2[g * H_ + threadIdx.x];
    if (threadIdx.x < K2_) {
        const int col = g * K2_ + threadIdx.x;
        float S = 0.f, Q = 0.f;
#pragma unroll
        for (int w = 0; w < NB1; w++) {
            S += d_p1s[w][col];
            Q += d_p1q[w][col];
        }
        float mean = S * INV_B;
        float var = Q * INV_B - mean * mean;
        float istd = rsqrtf(var + EPS);
        float scv = g1[col] * istd;
        sc[threadIdx.x] = scv;
        sf[threadIdx.x] = bt1[col] - mean * scv;
    }
    __syncthreads();

    const int b = blockIdx.y * 128 + threadIdx.x;
    const float4* xp = reinterpret_cast<const float4*>(
        d_a1 + (size_t)b * (L1G * H_) + g * K2_);

    unsigned long long acc[5];
#pragma unroll
    for (int p = 0; p < 5; p++) acc[p] = pack2(bsh[2 * p], bsh[2 * p + 1]);

#pragma unroll 5
    for (int j = 0; j < K2_ / 4; j++) {
        float4 xv = xp[j];
        const int k = 4 * j;
        fma10(acc, fmaf(xv.x, sc[k + 0], sf[k + 0]), &Wsh[(k + 0) * H_]);
        fma10(acc, fmaf(xv.y, sc[k + 1], sf[k + 1]), &Wsh[(k + 1) * H_]);
        fma10(acc, fmaf(xv.z, sc[k + 2], sf[k + 2]), &Wsh[(k + 2) * H_]);
        fma10(acc, fmaf(xv.w, sc[k + 3], sf[k + 3]), &Wsh[(k + 3) * H_]);
    }

    float v[H_];
#pragma unroll
    for (int p = 0; p < 5; p++) {
        float lo, hi;
        unpack2(acc[p], lo, hi);
        v[2 * p] = mishf(lo);
        v[2 * p + 1] = mishf(hi);
    }
    float* dst = d_a2 + (size_t)b * (L2G * H_) + g * H_;
#pragma unroll
    for (int p = 0; p < 5; p++)
        *reinterpret_cast<float2*>(dst + 2 * p) = make_float2(v[2 * p], v[2 * p + 1]);

    __syncthreads();
    block_stats10<4>(v, &d_p2s[blockIdx.y][g * H_], &d_p2q[blockIdx.y][g * H_],
                     threadIdx.x);
}

// ---------------------------------------------------------------------------
// K3: root linear.  grid(8), block 128. Finalizes level-2 BN inline.
// ---------------------------------------------------------------------------
__global__ void __launch_bounds__(128)
k_lvl3(const float* __restrict__ W3, const float* __restrict__ b3,
       const float* __restrict__ g2, const float* __restrict__ bt2) {
    __shared__ alignas(16) float Wsh[K3_ * H_];
    __shared__ float bsh[H_];
    __shared__ float sc[K3_], sf[K3_];
    for (int i = threadIdx.x; i < K3_ * H_; i += 128) Wsh[i] = W3[i];
    if (threadIdx.x < H_) bsh[threadIdx.x] = b3[threadIdx.x];
    for (int col = threadIdx.x; col < K3_; col += 128) {
        float S = 0.f, Q = 0.f;
#pragma unroll
        for (int w = 0; w < 8; w++) {
            S += d_p2s[w][col];
            Q += d_p2q[w][col];
        }
        float mean = S * INV_B;
        float var = Q * INV_B - mean * mean;
        float istd = rsqrtf(var + EPS);
        float scv = g2[col] * istd;
        sc[col] = scv;
        sf[col] = bt2[col] - mean * scv;
    }
    __syncthreads();

    const int b = blockIdx.x * 128 + threadIdx.x;
    const float4* xp = reinterpret_cast<const float4*>(d_a2 + (size_t)b * K3_);

    unsigned long long acc[5];
#pragma unroll
    for (int p = 0; p < 5; p++) acc[p] = pack2(bsh[2 * p], bsh[2 * p + 1]);

#pragma unroll 5
    for (int j = 0; j < K3_ / 4; j++) {
        float4 xv = xp[j];
        const int k = 4 * j;
        fma10(acc, fmaf(xv.x, sc[k + 0], sf[k + 0]), &Wsh[(k + 0) * H_]);
        fma10(acc, fmaf(xv.y, sc[k + 1], sf[k + 1]), &Wsh[(k + 1) * H_]);
        fma10(acc, fmaf(xv.z, sc[k + 2], sf[k + 2]), &Wsh[(k + 2) * H_]);
        fma10(acc, fmaf(xv.w, sc[k + 3], sf[k + 3]), &Wsh[(k + 3) * H_]);
    }

    float v[H_];
#pragma unroll
    for (int p = 0; p < 5; p++) {
        float lo, hi;
        unpack2(acc[p], lo, hi);
        v[2 * p] = mishf(lo);
        v[2 * p + 1] = mishf(hi);
    }
    float* dst = d_a3 + (size_t)b * H_;
#pragma unroll
    for (int p = 0; p < 5; p++)
        *reinterpret_cast<float2*>(dst + 2 * p) = make_float2(v[2 * p], v[2 * p + 1]);

    __syncthreads();
    block_stats10<4>(v, &d_p3s[blockIdx.x][0], &d_p3q[blockIdx.x][0], threadIdx.x);
}

// ---------------------------------------------------------------------------
// K4: finalize root BN + write output. 1 block, 1024 threads.
// ---------------------------------------------------------------------------
__global__ void __launch_bounds__(1024)
k_final(const float* __restrict__ g3, const float* __restrict__ bt3,
        float* __restrict__ out) {
    __shared__ float fsc[H_], fsf[H_];
    if (threadIdx.x < H_) {
        float S = 0.f, Q = 0.f;
#pragma unroll
        for (int w = 0; w < 8; w++) {
            S += d_p3s[w][threadIdx.x];
            Q += d_p3q[w][threadIdx.x];
        }
        float mean = S * INV_B;
        float var = Q * INV_B - mean * mean;
        float istd = rsqrtf(var + EPS);
        float scv = g3[threadIdx.x] * istd;
        fsc[threadIdx.x] = scv;
        fsf[threadIdx.x] = bt3[threadIdx.x] - mean * scv;
    }
    __syncthreads();
    const int b = threadIdx.x;
    const float2* row = reinterpret_cast<const float2*>(d_a3 + (size_t)b * H_);
    float2* orow = reinterpret_cast<float2*>(out + (size_t)b * H_);
#pragma unroll
    for (int p = 0; p < 5; p++) {
        float2 t = row[p];
        float2 o;
        o.x = fmaf(t.x, fsc[2 * p], fsf[2 * p]);
        o.y = fmaf(t.y, fsc[2 * p + 1], fsf[2 * p + 1]);
        orow[p] = o;
    }
}

// ---------------------------------------------------------------------------
// launch: exactly 4 kernel launches, no other runtime API calls.
// ---------------------------------------------------------------------------
extern "C" void kernel_launch(void* const* d_in, const int* in_sizes, int n_in,
                              void* d_out, int out_size) {
    const float* feat = (const float*)d_in[0];
    const float* W1  = (const float*)d_in[1];
    const float* b1  = (const float*)d_in[2];
    const float* g1  = (const float*)d_in[3];
    const float* bt1 = (const float*)d_in[4];
    const float* W2  = (const float*)d_in[5];
    const float* b2  = (const float*)d_in[6];
    const float* g2  = (const float*)d_in[7];
    const float* bt2 = (const float*)d_in[8];
    const float* W3  = (const float*)d_in[9];
    const float* b3  = (const float*)d_in[10];
    const float* g3  = (const float*)d_in[11];
    const float* bt3 = (const float*)d_in[12];
    float* out = (float*)d_out;

    k_lvl1<<<dim3(L1G, NB1), 256>>>(feat, W1, b1);
    k_lvl2<<<dim3(L2G, B_ / 128), 128>>>(W2, b2, g1, bt1);
    k_lvl3<<<B_ / 128, 128>>>(W3, b3, g2, bt2);
    k_final<<<1, B_>>>(g3, bt3, out);
}